// round 11
// baseline (speedup 1.0000x reference)
#include <cuda_runtime.h>
#include <float.h>

#define THRESHOLD 0.5f
#define B 256
#define HW 49            // 7*7
#define C_INTERM 1000
#define C_VGG 512
#define F4_PER_BATCH (HW * C_VGG / 4)       // 6272
#define PARTS 4
#define F4_PER_PART (F4_PER_BATCH / PARTS)  // 1568 = 6*256 + 32

// 16-byte cp.async, .cg = L2-cached, no register file involvement.
__device__ __forceinline__ void cp_async16(void* smem_dst, const void* gmem_src) {
    unsigned s = (unsigned)__cvta_generic_to_shared(smem_dst);
    asm volatile("cp.async.cg.shared.global [%0], [%1], 16;\n"
                 :: "r"(s), "l"(gmem_src) : "memory");
}
__device__ __forceinline__ void cp_async_commit() {
    asm volatile("cp.async.commit_group;\n" ::: "memory");
}
__device__ __forceinline__ void cp_async_wait_all() {
    asm volatile("cp.async.wait_group 0;\n" ::: "memory");
}

// ---------------------------------------------------------------------------
// Fused kernel, 4 blocks per batch, SINGLE barrier:
//   Phase 0: cp.async quarter-batch (25KB) into smem
//   Phase A: argmax (warp butterfly -> smem partials -> ONE barrier ->
//            every thread reduces 8 partials to idx locally)
//   Phase A': each thread direct-LDGs its own needed CAM values (no gather
//             stage, no second barrier; per-warp these are 1-2 lines per k)
//   Phase B: wait own cp.asyncs -> subtract -> store (warps fully
//            independent after the single barrier)
// ---------------------------------------------------------------------------
__global__ __launch_bounds__(256) void fused_kernel(
    const float*  __restrict__ branchA,  // [B, 1000]
    const float*  __restrict__ interm,   // [B, 49, 1000]
    const float4* __restrict__ vgg,      // [B*49*512/4]
    float4*       __restrict__ out)
{
    __shared__ float4 s_buf[F4_PER_PART];   // 25,088 B
    __shared__ float  s_wv[8];
    __shared__ int    s_wi[8];

    const int b    = blockIdx.x >> 2;
    const int part = blockIdx.x & 3;
    const int tid  = threadIdx.x;
    const int lane = tid & 31;
    const int wid  = tid >> 5;

    const int loc0  = part * F4_PER_PART + tid;   // local f4 index in batch
    const int base4 = b * F4_PER_BATCH + loc0;    // global f4 index

    // ---------------- Phase 0: async-copy quarter into smem -----------------
    #pragma unroll
    for (int k = 0; k < 6; k++)
        cp_async16(&s_buf[tid + k * 256], &vgg[base4 + k * 256]);
    if (tid < 32)
        cp_async16(&s_buf[tid + 6 * 256], &vgg[base4 + 6 * 256]);
    cp_async_commit();

    // ---------------- Phase A: argmax (first-index-wins) -------------------
    const float4* row4 = (const float4*)(branchA + (size_t)b * C_INTERM);

    float best_v = -FLT_MAX;
    int   best_i = C_INTERM;
    if (tid < 250) {                       // 250 float4 = 1000 floats
        float4 x = __ldg(row4 + tid);
        const int i0 = tid * 4;
        if (x.x > best_v) { best_v = x.x; best_i = i0; }
        if (x.y > best_v) { best_v = x.y; best_i = i0 + 1; }
        if (x.z > best_v) { best_v = x.z; best_i = i0 + 2; }
        if (x.w > best_v) { best_v = x.w; best_i = i0 + 3; }
    }

    #pragma unroll
    for (int off = 16; off > 0; off >>= 1) {
        float ov = __shfl_xor_sync(0xFFFFFFFFu, best_v, off);
        int   oi = __shfl_xor_sync(0xFFFFFFFFu, best_i, off);
        if (ov > best_v || (ov == best_v && oi < best_i)) { best_v = ov; best_i = oi; }
    }

    if (lane == 0) { s_wv[wid] = best_v; s_wi[wid] = best_i; }
    __syncthreads();                       // the ONLY block barrier

    int idx;
    {
        float fv = s_wv[0]; int fi = s_wi[0];
        #pragma unroll
        for (int k = 1; k < 8; k++) {
            float ov = s_wv[k]; int oi = s_wi[k];
            if (ov > fv || (ov == fv && oi < fi)) { fv = ov; fi = oi; }
        }
        idx = fi;
    }

    // ---------------- Phase A': direct per-thread CAM loads -----------------
    // Thread's k-th element lives in cell (loc0 + k*256) >> 7. Issue all 6
    // (+tail) loads at once; within a warp each k maps to 1-2 distinct
    // addresses -> broadcast wavefronts, L1/L2 dedup.
    const float* cam = interm + (size_t)b * HW * C_INTERM + idx;
    float t[6];
    #pragma unroll
    for (int k = 0; k < 6; k++) {
        float a = __ldg(cam + ((loc0 + k * 256) >> 7) * C_INTERM);
        t[k] = (a > THRESHOLD) ? a : 0.0f;
    }
    float t6 = 0.0f;
    if (tid < 32) {
        float a = __ldg(cam + ((loc0 + 6 * 256) >> 7) * C_INTERM);
        t6 = (a > THRESHOLD) ? a : 0.0f;
    }

    // ---------------- Phase B: wait own copies -> subtract -> store ----------
    cp_async_wait_all();     // same-thread data; no barrier needed

    #pragma unroll
    for (int k = 0; k < 6; k++) {
        float4 r = s_buf[tid + k * 256];
        r.x -= t[k]; r.y -= t[k]; r.z -= t[k]; r.w -= t[k];
        out[base4 + k * 256] = r;
    }
    if (tid < 32) {
        float4 r = s_buf[tid + 6 * 256];
        r.x -= t6; r.y -= t6; r.z -= t6; r.w -= t6;
        out[base4 + 6 * 256] = r;
    }
}

extern "C" void kernel_launch(void* const* d_in, const int* in_sizes, int n_in,
                              void* d_out, int out_size) {
    const float* vgg_end = (const float*)d_in[0];  // [256,7,7,512]
    const float* interm  = (const float*)d_in[1];  // [256,7,7,1000]
    const float* branchA = (const float*)d_in[2];  // [256,1000]
    float*       out     = (float*)d_out;

    static bool configured = false;
    if (!configured) {
        cudaFuncSetAttribute(fused_kernel,
                             cudaFuncAttributePreferredSharedMemoryCarveout, 100);
        configured = true;
    }

    fused_kernel<<<B * PARTS, 256>>>(branchA, interm,
                                     (const float4*)vgg_end, (float4*)out);
}

// round 12
// speedup vs baseline: 1.0025x; 1.0025x over previous
#include <cuda_runtime.h>
#include <float.h>

#define THRESHOLD 0.5f
#define B 256
#define HW 49            // 7*7
#define C_INTERM 1000
#define C_VGG 512
#define F4_PER_BATCH (HW * C_VGG / 4)       // 6272
#define PARTS 2
#define F4_PER_PART (F4_PER_BATCH / PARTS)  // 3136 = 6*512 + 64
#define THREADS 512
#define SMEM_BYTES (F4_PER_PART * 16)       // 50,176 B (dynamic)

// 16-byte cp.async, .cg = L2-cached, no register file involvement.
__device__ __forceinline__ void cp_async16(void* smem_dst, const void* gmem_src) {
    unsigned s = (unsigned)__cvta_generic_to_shared(smem_dst);
    asm volatile("cp.async.cg.shared.global [%0], [%1], 16;\n"
                 :: "r"(s), "l"(gmem_src) : "memory");
}
__device__ __forceinline__ void cp_async_commit() {
    asm volatile("cp.async.commit_group;\n" ::: "memory");
}
__device__ __forceinline__ void cp_async_wait_all() {
    asm volatile("cp.async.wait_group 0;\n" ::: "memory");
}

// ---------------------------------------------------------------------------
// Fused kernel, 2 blocks per batch, 512 threads (halves redundant argmax):
//   Phase 0: cp.async this block's half-batch (50KB) into dynamic smem
//   Phase A: argmax over branchA[b,:] (first-index-wins), gather CAM -> s_t
//   Phase B: smem -> subtract -> store
// ---------------------------------------------------------------------------
__global__ __launch_bounds__(THREADS) void fused_kernel(
    const float*  __restrict__ branchA,  // [B, 1000]
    const float*  __restrict__ interm,   // [B, 49, 1000]
    const float4* __restrict__ vgg,      // [B*49*512/4]
    float4*       __restrict__ out)
{
    extern __shared__ float4 s_buf[];       // F4_PER_PART entries
    __shared__ float  s_t[HW];
    __shared__ float  s_wv[16];
    __shared__ int    s_wi[16];

    const int b    = blockIdx.x >> 1;
    const int part = blockIdx.x & 1;
    const int tid  = threadIdx.x;
    const int lane = tid & 31;
    const int wid  = tid >> 5;

    const int loc0  = part * F4_PER_PART + tid;   // local f4 index in batch
    const int base4 = b * F4_PER_BATCH + loc0;    // global f4 index

    // ---------------- Phase 0: async-copy half-batch into smem --------------
    #pragma unroll
    for (int k = 0; k < 6; k++)
        cp_async16(&s_buf[tid + k * THREADS], &vgg[base4 + k * THREADS]);
    if (tid < 64)
        cp_async16(&s_buf[tid + 6 * THREADS], &vgg[base4 + 6 * THREADS]);
    cp_async_commit();

    // ---------------- Phase A: argmax (first-index-wins) -------------------
    const float4* row4 = (const float4*)(branchA + (size_t)b * C_INTERM);

    float best_v = -FLT_MAX;
    int   best_i = C_INTERM;
    if (tid < 250) {                       // 250 float4 = 1000 floats
        float4 x = __ldg(row4 + tid);
        const int i0 = tid * 4;
        if (x.x > best_v) { best_v = x.x; best_i = i0; }
        if (x.y > best_v) { best_v = x.y; best_i = i0 + 1; }
        if (x.z > best_v) { best_v = x.z; best_i = i0 + 2; }
        if (x.w > best_v) { best_v = x.w; best_i = i0 + 3; }
    }

    #pragma unroll
    for (int off = 16; off > 0; off >>= 1) {
        float ov = __shfl_xor_sync(0xFFFFFFFFu, best_v, off);
        int   oi = __shfl_xor_sync(0xFFFFFFFFu, best_i, off);
        if (ov > best_v || (ov == best_v && oi < best_i)) { best_v = ov; best_i = oi; }
    }

    if (lane == 0) { s_wv[wid] = best_v; s_wi[wid] = best_i; }
    __syncthreads();

    // Every thread reduces the 16 partials serially (broadcast smem reads).
    int idx;
    {
        float fv = s_wv[0]; int fi = s_wi[0];
        #pragma unroll
        for (int k = 1; k < 16; k++) {
            float ov = s_wv[k]; int oi = s_wi[k];
            if (ov > fv || (ov == fv && oi < fi)) { fv = ov; fi = oi; }
        }
        idx = fi;
    }

    // Gather + threshold the 49 CAM values for this batch.
    if (tid < HW) {
        float a = __ldg(interm + ((size_t)b * HW + tid) * C_INTERM + idx);
        s_t[tid] = (a > THRESHOLD) ? a : 0.0f;
    }

    // Same-thread cp.async data: wait_group 0 covers s_buf; barrier covers s_t.
    cp_async_wait_all();
    __syncthreads();

    // ---------------- Phase B: smem -> subtract -> store ---------------------
    #pragma unroll
    for (int k = 0; k < 6; k++) {
        const float tv = s_t[(loc0 + k * THREADS) >> 7];   // 128 f4 per cell
        float4 r = s_buf[tid + k * THREADS];
        r.x -= tv; r.y -= tv; r.z -= tv; r.w -= tv;
        out[base4 + k * THREADS] = r;
    }
    if (tid < 64) {
        const float tv = s_t[(loc0 + 6 * THREADS) >> 7];
        float4 r = s_buf[tid + 6 * THREADS];
        r.x -= tv; r.y -= tv; r.z -= tv; r.w -= tv;
        out[base4 + 6 * THREADS] = r;
    }
}

extern "C" void kernel_launch(void* const* d_in, const int* in_sizes, int n_in,
                              void* d_out, int out_size) {
    const float* vgg_end = (const float*)d_in[0];  // [256,7,7,512]
    const float* interm  = (const float*)d_in[1];  // [256,7,7,1000]
    const float* branchA = (const float*)d_in[2];  // [256,1000]
    float*       out     = (float*)d_out;

    static bool configured = false;
    if (!configured) {
        cudaFuncSetAttribute(fused_kernel,
                             cudaFuncAttributeMaxDynamicSharedMemorySize, SMEM_BYTES);
        cudaFuncSetAttribute(fused_kernel,
                             cudaFuncAttributePreferredSharedMemoryCarveout, 100);
        configured = true;
    }

    fused_kernel<<<B * PARTS, THREADS, SMEM_BYTES>>>(
        branchA, interm, (const float4*)vgg_end, (float4*)out);
}

// round 13
// speedup vs baseline: 1.1976x; 1.1946x over previous
#include <cuda_runtime.h>
#include <float.h>

#define THRESHOLD 0.5f
#define B 256
#define HW 49            // 7*7
#define C_INTERM 1000
#define C_VGG 512
#define F4_PER_BATCH (HW * C_VGG / 4)       // 6272
#define PARTS 4
#define F4_PER_PART (F4_PER_BATCH / PARTS)  // 1568 = 6*256 + 32

// 16-byte cp.async, .cg = L2-cached, no register file involvement.
__device__ __forceinline__ void cp_async16(void* smem_dst, const void* gmem_src) {
    unsigned s = (unsigned)__cvta_generic_to_shared(smem_dst);
    asm volatile("cp.async.cg.shared.global [%0], [%1], 16;\n"
                 :: "r"(s), "l"(gmem_src) : "memory");
}
__device__ __forceinline__ void cp_async_commit() {
    asm volatile("cp.async.commit_group;\n" ::: "memory");
}
__device__ __forceinline__ void cp_async_wait_all() {
    asm volatile("cp.async.wait_group 0;\n" ::: "memory");
}

// ---------------------------------------------------------------------------
// Fused kernel, 4 blocks/batch (R7 geometry). Prologue confined to warps 0-1:
//   all warps: issue cp.asyncs for the quarter-batch (25KB)
//   warps 0-1: scan branchA row (64 thr x 4 float4), butterfly-reduce,
//              publish 2 partials; after bar1 all compute idx; tid<49
//              (warps 0-1) gather CAM -> s_t
//   warps 2-7: nothing between cp.async issue and the barriers (sleep)
//   all warps: wait own copies -> subtract -> store
// ---------------------------------------------------------------------------
__global__ __launch_bounds__(256) void fused_kernel(
    const float*  __restrict__ branchA,  // [B, 1000]
    const float*  __restrict__ interm,   // [B, 49, 1000]
    const float4* __restrict__ vgg,      // [B*49*512/4]
    float4*       __restrict__ out)
{
    __shared__ float4 s_buf[F4_PER_PART];   // 25,088 B
    __shared__ float  s_t[HW];
    __shared__ float  s_wv[2];
    __shared__ int    s_wi[2];

    const int b    = blockIdx.x >> 2;
    const int part = blockIdx.x & 3;
    const int tid  = threadIdx.x;
    const int lane = tid & 31;
    const int wid  = tid >> 5;

    const int loc0  = part * F4_PER_PART + tid;   // local f4 index in batch
    const int base4 = b * F4_PER_BATCH + loc0;    // global f4 index

    // ---------------- Phase 0: async-copy quarter into smem -----------------
    #pragma unroll
    for (int k = 0; k < 6; k++)
        cp_async16(&s_buf[tid + k * 256], &vgg[base4 + k * 256]);
    if (tid < 32)
        cp_async16(&s_buf[tid + 6 * 256], &vgg[base4 + 6 * 256]);
    cp_async_commit();

    // ---------------- Phase A: argmax on warps 0-1 only ---------------------
    if (wid < 2) {
        const float4* row4 = (const float4*)(branchA + (size_t)b * C_INTERM);

        float best_v = -FLT_MAX;
        int   best_i = C_INTERM;
        // 64 threads x 4 float4 = 256 f4 >= 250; all 4 loads independent.
        #pragma unroll
        for (int k = 0; k < 4; k++) {
            const int f4i = tid + k * 64;
            if (f4i < 250) {
                float4 x = __ldg(row4 + f4i);
                const int i0 = f4i * 4;
                if (x.x > best_v) { best_v = x.x; best_i = i0; }
                if (x.y > best_v) { best_v = x.y; best_i = i0 + 1; }
                if (x.z > best_v) { best_v = x.z; best_i = i0 + 2; }
                if (x.w > best_v) { best_v = x.w; best_i = i0 + 3; }
            }
        }

        #pragma unroll
        for (int off = 16; off > 0; off >>= 1) {
            float ov = __shfl_xor_sync(0xFFFFFFFFu, best_v, off);
            int   oi = __shfl_xor_sync(0xFFFFFFFFu, best_i, off);
            if (ov > best_v || (ov == best_v && oi < best_i)) { best_v = ov; best_i = oi; }
        }
        if (lane == 0) { s_wv[wid] = best_v; s_wi[wid] = best_i; }
    }
    __syncthreads();          // bar1: partials (warps 2-7 arrive early, sleep)

    // Gather + threshold the 49 CAM values (threads 0..48 = warps 0-1).
    if (tid < HW) {
        int idx;
        {
            float fv = s_wv[0]; int fi = s_wi[0];
            float ov = s_wv[1]; int oi = s_wi[1];
            idx = (ov > fv || (ov == fv && oi < fi)) ? oi : fi;
        }
        float a = __ldg(interm + ((size_t)b * HW + tid) * C_INTERM + idx);
        s_t[tid] = (a > THRESHOLD) ? a : 0.0f;
    }

    // Same-thread cp.async data: wait_group 0 covers s_buf; bar2 covers s_t.
    cp_async_wait_all();
    __syncthreads();          // bar2: s_t visible

    // ---------------- Phase B: smem -> subtract -> store ---------------------
    #pragma unroll
    for (int k = 0; k < 6; k++) {
        const float tv = s_t[(loc0 + k * 256) >> 7];   // 128 f4 per cell
        float4 r = s_buf[tid + k * 256];
        r.x -= tv; r.y -= tv; r.z -= tv; r.w -= tv;
        out[base4 + k * 256] = r;
    }
    if (tid < 32) {
        const float tv = s_t[(loc0 + 6 * 256) >> 7];
        float4 r = s_buf[tid + 6 * 256];
        r.x -= tv; r.y -= tv; r.z -= tv; r.w -= tv;
        out[base4 + 6 * 256] = r;
    }
}

extern "C" void kernel_launch(void* const* d_in, const int* in_sizes, int n_in,
                              void* d_out, int out_size) {
    const float* vgg_end = (const float*)d_in[0];  // [256,7,7,512]
    const float* interm  = (const float*)d_in[1];  // [256,7,7,1000]
    const float* branchA = (const float*)d_in[2];  // [256,1000]
    float*       out     = (float*)d_out;

    fused_kernel<<<B * PARTS, 256>>>(branchA, interm,
                                     (const float4*)vgg_end, (float4*)out);
}